// round 1
// baseline (speedup 1.0000x reference)
#include <cuda_runtime.h>
#include <cstdint>

#define Bn 256
#define Sn 512
#define Kn 32
#define Fn 64
#define H1n 512
#define H2n 256

// Scratch (allocation-free rule: __device__ globals)
__device__ float    g_c1[Sn * H1n];          // b1[h] + sum_k dist[s,k]*W1[k*65+64, h]
__device__ unsigned g_m[Bn * H2n];           // bits of max_s relu(h2)  (>=0 so uint order == float order)

// SMEM layout constants
#define APAD 68                               // 64 + 4, float4-aligned rows
#define HPAD 520                              // 512 + 8, float4-aligned rows
#define SM_AS   (64 * APAD)                   // 4352 floats
#define SM_BS   (64 * 256)                    // 16384 floats
#define SM_HS   (64 * HPAD)                   // 33280 floats
#define SMEM_FLOATS (SM_AS + SM_BS + SM_HS)   // 54016 floats = 216064 B

__global__ void zero_m_kernel() {
    int i = blockIdx.x * blockDim.x + threadIdx.x;
    if (i < Bn * H2n) g_m[i] = 0u;
}

// c1[s][h] = b1[h] + sum_k dist[s,k] * W1[k*65+64, h]
__global__ void prep_c1_kernel(const float* __restrict__ W1,
                               const float* __restrict__ b1,
                               const float* __restrict__ dist) {
    int s = blockIdx.x;
    int h = threadIdx.x;           // 512 threads
    float acc = b1[h];
#pragma unroll
    for (int k = 0; k < Kn; k++) {
        acc = fmaf(dist[s * Kn + k], W1[(k * 65 + 64) * H1n + h], acc);
    }
    g_c1[s * H1n + h] = acc;
}

// 8x8 micro-tile rank-64 update: acc += A[0:64 rows x 64 f] * B[64 f x 256]
// A is read at row stride ASTR (broadcast within warp), B is [64][256].
__device__ __forceinline__ void mm_tile64(const float* __restrict__ A, int ASTR,
                                          const float* __restrict__ B,
                                          float acc[8][8], int ty, int tx) {
#pragma unroll 4
    for (int f = 0; f < 64; f += 2) {
        float2 av[8];
#pragma unroll
        for (int i = 0; i < 8; i++)
            av[i] = *(const float2*)(A + (ty * 8 + i) * ASTR + f);
        float4 b0a = *(const float4*)(B + f * 256 + tx * 8);
        float4 b0b = *(const float4*)(B + f * 256 + tx * 8 + 4);
        float4 b1a = *(const float4*)(B + (f + 1) * 256 + tx * 8);
        float4 b1b = *(const float4*)(B + (f + 1) * 256 + tx * 8 + 4);
        float bj0[8] = {b0a.x, b0a.y, b0a.z, b0a.w, b0b.x, b0b.y, b0b.z, b0b.w};
        float bj1[8] = {b1a.x, b1a.y, b1a.z, b1a.w, b1b.x, b1b.y, b1b.z, b1b.w};
#pragma unroll
        for (int i = 0; i < 8; i++)
#pragma unroll
            for (int j = 0; j < 8; j++)
                acc[i][j] = fmaf(av[i].x, bj0[j], acc[i][j]);
#pragma unroll
        for (int i = 0; i < 8; i++)
#pragma unroll
            for (int j = 0; j < 8; j++)
                acc[i][j] = fmaf(av[i].y, bj1[j], acc[i][j]);
    }
}

// One block per (s, 64-batch tile). Computes h1 (64x512) into SMEM, then
// h2 (64x256) and atomic-max-reduces relu(h2) into g_m.
__global__ __launch_bounds__(256, 1)
void fused_kernel(const float* __restrict__ x,
                  const int*   __restrict__ nbh,
                  const float* __restrict__ W1,
                  const float* __restrict__ W2,
                  const float* __restrict__ b2) {
    extern __shared__ float sm[];
    float* As = sm;                  // [64][APAD]   gathered x tile (b x f)
    float* Bs = sm + SM_AS;          // [64][256]    weight tile
    float* Hs = sm + SM_AS + SM_BS;  // [64][HPAD]   relu(h1) tile (b x h1col)

    const int s  = blockIdx.y;
    const int b0 = blockIdx.x * 64;
    const int tid = threadIdx.x;
    const int ty = tid >> 5;         // 0..7  -> row group (8 rows)
    const int tx = tid & 31;         // 0..31 -> col group (8 cols)

    // ---------------- Phase 1: h1 = relu(gather @ W1 + c1) ----------------
    for (int n1 = 0; n1 < 2; n1++) {
        float acc[8][8];
#pragma unroll
        for (int i = 0; i < 8; i++)
#pragma unroll
            for (int j = 0; j < 8; j++) acc[i][j] = 0.f;

        for (int k = 0; k < Kn; k++) {
            const int nidx = __ldg(&nbh[s * Kn + k]);
            // Load A: x[b0+row, nidx, 0:64] -> As[row][f]
            {
                const int row = tid >> 2;
                const int fb  = (tid & 3) * 16;
                const float* src = x + ((size_t)(b0 + row) * Sn + nidx) * Fn + fb;
                float* dst = As + row * APAD + fb;
#pragma unroll
                for (int q = 0; q < 4; q++)
                    *(float4*)(dst + q * 4) = *(const float4*)(src + q * 4);
            }
            // Load B: W1[k*65 + (0:64), n1*256 + (0:256)] -> Bs[r][c]
            {
                const float* wsrc = W1 + (size_t)(k * 65) * H1n + n1 * 256;
#pragma unroll
                for (int it = 0; it < 16; it++) {
                    int l = tid * 4 + it * 1024;
                    int r = l >> 8, c = l & 255;
                    *(float4*)(Bs + r * 256 + c) =
                        *(const float4*)(wsrc + (size_t)r * H1n + c);
                }
            }
            __syncthreads();
            mm_tile64(As, APAD, Bs, acc, ty, tx);
            __syncthreads();
        }

        // Epilogue: + c1[s], relu, stage into Hs
        {
            float cc[8];
#pragma unroll
            for (int j = 0; j < 8; j++)
                cc[j] = __ldg(&g_c1[s * H1n + n1 * 256 + tx * 8 + j]);
#pragma unroll
            for (int i = 0; i < 8; i++) {
                float v[8];
#pragma unroll
                for (int j = 0; j < 8; j++)
                    v[j] = fmaxf(acc[i][j] + cc[j], 0.f);
                float* dst = Hs + (ty * 8 + i) * HPAD + n1 * 256 + tx * 8;
                *(float4*)(dst)     = make_float4(v[0], v[1], v[2], v[3]);
                *(float4*)(dst + 4) = make_float4(v[4], v[5], v[6], v[7]);
            }
        }
    }
    __syncthreads();   // Hs fully written

    // ---------------- Phase 2: h2 = h1 @ W2 + b2 ----------------
    float acc2[8][8];
#pragma unroll
    for (int i = 0; i < 8; i++)
#pragma unroll
        for (int j = 0; j < 8; j++) acc2[i][j] = 0.f;

    for (int kk = 0; kk < H1n; kk += 64) {
        // Load W2[kk + (0:64), 0:256] -> Bs
        const float* wsrc = W2 + (size_t)kk * H2n;
#pragma unroll
        for (int it = 0; it < 16; it++) {
            int l = tid * 4 + it * 1024;
            int r = l >> 8, c = l & 255;
            *(float4*)(Bs + r * 256 + c) =
                *(const float4*)(wsrc + (size_t)r * H2n + c);
        }
        __syncthreads();
        mm_tile64(Hs + kk, HPAD, Bs, acc2, ty, tx);
        __syncthreads();
    }

    // Epilogue: + b2, relu, atomic max into g_m (uint bits, values >= 0)
    {
        float bb[8];
#pragma unroll
        for (int j = 0; j < 8; j++)
            bb[j] = __ldg(&b2[tx * 8 + j]);
#pragma unroll
        for (int i = 0; i < 8; i++) {
            const int b = b0 + ty * 8 + i;
#pragma unroll
            for (int j = 0; j < 8; j++) {
                float v = fmaxf(acc2[i][j] + bb[j], 0.f);
                atomicMax(&g_m[b * H2n + tx * 8 + j], __float_as_uint(v));
            }
        }
    }
}

// out[b] = bd + sum_n m[b][n] * Wd[n]
__global__ void finalize_kernel(const float* __restrict__ Wd,
                                const float* __restrict__ bd,
                                float* __restrict__ out) {
    __shared__ float red[256];
    const int b = blockIdx.x;
    const int t = threadIdx.x;   // 256 threads
    red[t] = __uint_as_float(g_m[b * H2n + t]) * Wd[t];
    __syncthreads();
#pragma unroll
    for (int st = 128; st > 0; st >>= 1) {
        if (t < st) red[t] += red[t + st];
        __syncthreads();
    }
    if (t == 0) out[b] = red[0] + bd[0];
}

extern "C" void kernel_launch(void* const* d_in, const int* in_sizes, int n_in,
                              void* d_out, int out_size) {
    const float* x    = (const float*)d_in[0];
    const int*   nbh  = (const int*)  d_in[1];
    const float* dist = (const float*)d_in[2];
    const float* W1   = (const float*)d_in[3];
    const float* b1   = (const float*)d_in[4];
    const float* W2   = (const float*)d_in[5];
    const float* b2   = (const float*)d_in[6];
    const float* Wd   = (const float*)d_in[7];
    const float* bd   = (const float*)d_in[8];
    float* out = (float*)d_out;

    static bool attr_set = false;
    if (!attr_set) {
        cudaFuncSetAttribute(fused_kernel,
                             cudaFuncAttributeMaxDynamicSharedMemorySize,
                             SMEM_FLOATS * sizeof(float));
        attr_set = true;
    }

    zero_m_kernel<<<(Bn * H2n + 255) / 256, 256>>>();
    prep_c1_kernel<<<Sn, H1n>>>(W1, b1, dist);
    fused_kernel<<<dim3(Bn / 64, Sn), 256, SMEM_FLOATS * sizeof(float)>>>(x, nbh, W1, W2, b2);
    finalize_kernel<<<Bn, H2n>>>(Wd, bd, out);
}

// round 4
// speedup vs baseline: 3.4751x; 3.4751x over previous
#include <cuda_runtime.h>
#include <cstdint>

#define Bn 256
#define Sn 512
#define Kn 32
#define Fn 64
#define H1n 512
#define H2n 256

// ---------------- device scratch (allocation-free rule) ----------------
__device__ float    g_c1[Sn * H1n];        // fp32: b1 + dist-column contribution
__device__ unsigned g_m[Bn * H2n];         // bits of max_s relu(h2)
__device__ float    g_w1t[H1n * 2048];     // [n][k], k = nb*64+f, tf32-rounded
__device__ float    g_w2t[H2n * H1n];      // [n2][h1], tf32-rounded
__device__ float    g_xr[Bn * Sn * Fn];    // tf32-rounded x

// ---------------- smem layout (floats) ----------------
#define ASTG 4608                   // 128 rows * 36
#define BSTG 4608                   // 128 rows * 36
#define AS_OFF 0
#define BS_OFF (3 * ASTG)           // 13824
#define HS_OFF (BS_OFF + 3 * BSTG)  // 27648
#define HSTR 132
#define SMEM_FLOATS (HS_OFF + 128 * HSTR)   // 44544 floats = 178176 B

// ---------------- PTX helpers ----------------
__device__ __forceinline__ uint32_t smem_u32(const void* p) {
    uint32_t a;
    asm("{ .reg .u64 t; cvta.to.shared.u64 t, %1; cvt.u32.u64 %0, t; }" : "=r"(a) : "l"(p));
    return a;
}
__device__ __forceinline__ uint32_t f2tf32(float f) {
    uint32_t r; asm("cvt.rna.tf32.f32 %0, %1;" : "=r"(r) : "f"(f)); return r;
}
__device__ __forceinline__ void cpasync16(uint32_t s, const void* g) {
    asm volatile("cp.async.cg.shared.global [%0], [%1], 16;" :: "r"(s), "l"(g));
}
#define CP_COMMIT() asm volatile("cp.async.commit_group;")
#define CP_WAIT2()  asm volatile("cp.async.wait_group 2;")
#define CP_WAIT1()  asm volatile("cp.async.wait_group 1;")

__device__ __forceinline__ void mma8(float* d, uint32_t a0, uint32_t a1, uint32_t a2,
                                     uint32_t a3, uint32_t b0, uint32_t b1) {
    asm volatile(
        "mma.sync.aligned.m16n8k8.row.col.f32.tf32.tf32.f32 "
        "{%0,%1,%2,%3}, {%4,%5,%6,%7}, {%8,%9}, {%0,%1,%2,%3};"
        : "+f"(d[0]), "+f"(d[1]), "+f"(d[2]), "+f"(d[3])
        : "r"(a0), "r"(a1), "r"(a2), "r"(a3), "r"(b0), "r"(b1));
}
__device__ __forceinline__ uint32_t fu(float f) { return __float_as_uint(f); }

// ---------------- prep kernels ----------------
__global__ void zero_m_kernel() {
    int i = blockIdx.x * blockDim.x + threadIdx.x;
    if (i < Bn * H2n) g_m[i] = 0u;
}
__global__ void prep_xr_kernel(const float* __restrict__ x) {
    int i = blockIdx.x * 256 + threadIdx.x;
    g_xr[i] = __uint_as_float(f2tf32(x[i]));
}
__global__ void prep_w1t_kernel(const float* __restrict__ W1) {
    int idx = blockIdx.x * 256 + threadIdx.x;   // 512*2048
    int k = idx & 2047, n = idx >> 11;
    int row = (k >> 6) * 65 + (k & 63);
    g_w1t[(size_t)n * 2048 + k] = __uint_as_float(f2tf32(W1[(size_t)row * H1n + n]));
}
__global__ void prep_w2t_kernel(const float* __restrict__ W2) {
    int idx = blockIdx.x * 256 + threadIdx.x;   // 256*512
    int h = idx & 511, n = idx >> 9;
    g_w2t[(size_t)n * H1n + h] = __uint_as_float(f2tf32(W2[(size_t)h * H2n + n]));
}
__global__ void prep_c1_kernel(const float* __restrict__ W1,
                               const float* __restrict__ b1,
                               const float* __restrict__ dist) {
    int s = blockIdx.x, h = threadIdx.x;
    float acc = b1[h];
#pragma unroll
    for (int k = 0; k < Kn; k++)
        acc = fmaf(dist[s * Kn + k], W1[(k * 65 + 64) * H1n + h], acc);
    g_c1[s * H1n + h] = acc;
}

// ---------------- load helpers ----------------
__device__ __forceinline__ void issue_g1(int c, int n1, int st, int tid,
                                         uint32_t smb, const int* __restrict__ nbh_s,
                                         int b0) {
    const int nb = c >> 1, f0 = (c & 1) * 32;
    const int sidx = __ldg(&nbh_s[nb]);
    const uint32_t ab = smb + (uint32_t)(AS_OFF + st * ASTG) * 4u;
    const float* asrc = g_xr + ((size_t)b0 * Sn + sidx) * Fn + f0;
#pragma unroll
    for (int p = 0; p < 4; p++) {
        int u = tid + p * 256; int r = u >> 3, q = u & 7;
        cpasync16(ab + (uint32_t)(r * 144 + q * 16),
                  asrc + (size_t)r * (Sn * Fn) + q * 4);
    }
    const uint32_t bb = smb + (uint32_t)(BS_OFF + st * BSTG) * 4u;
    const float* bsrc = g_w1t + (size_t)(n1 * 128) * 2048 + c * 32;
#pragma unroll
    for (int p = 0; p < 4; p++) {
        int u = tid + p * 256; int r = u >> 3, q = u & 7;
        cpasync16(bb + (uint32_t)(r * 144 + q * 16),
                  bsrc + (size_t)r * 2048 + q * 4);
    }
}
__device__ __forceinline__ void issue_g2(int n1, int kc, int bufoff, int tid,
                                         uint32_t smb) {
    const uint32_t bb = smb + (uint32_t)bufoff * 4u;
    const float* bsrc = g_w2t + n1 * 128 + kc * 32;
#pragma unroll
    for (int p = 0; p < 8; p++) {
        int u = tid + p * 256; int n = u >> 3, q = u & 7;
        cpasync16(bb + (uint32_t)(n * 144 + q * 16),
                  bsrc + (size_t)n * H1n + q * 4);
    }
}

// ---------------- fused mma.sync kernel ----------------
__global__ __launch_bounds__(256, 1)
void fused_mma_kernel(const int* __restrict__ nbh, const float* __restrict__ b2) {
    extern __shared__ float sm[];
    const int tid = threadIdx.x, lane = tid & 31, wid = tid >> 5;
    const int gid = lane >> 2, tig = lane & 3;
    const int wm = (wid >> 1) * 32;     // warp M offset (0,32,64,96)
    const int wn = wid & 1;             // warp N half
    const int s = blockIdx.y, b0 = blockIdx.x * 128;
    const int* nbh_s = nbh + s * Kn;
    const uint32_t smb = smem_u32(sm);

    float acc2[2][16][4];
#pragma unroll
    for (int mt = 0; mt < 2; mt++)
#pragma unroll
        for (int nt = 0; nt < 16; nt++)
#pragma unroll
            for (int i = 0; i < 4; i++) acc2[mt][nt][i] = 0.f;

    for (int n1 = 0; n1 < 4; n1++) {
        float acc1[2][8][4];
#pragma unroll
        for (int mt = 0; mt < 2; mt++)
#pragma unroll
            for (int nt = 0; nt < 8; nt++)
#pragma unroll
                for (int i = 0; i < 4; i++) acc1[mt][nt][i] = 0.f;

        // prologue: 3 chunks in flight
#pragma unroll
        for (int c = 0; c < 3; c++) {
            issue_g1(c, n1, c, tid, smb, nbh_s, b0);
            CP_COMMIT();
        }

        // -------- GEMM1 mainloop: 64 chunks of k=32 --------
        for (int c = 0; c < 64; c++) {
            CP_WAIT2();
            __syncthreads();
            const int st = c % 3;
            const float* A  = sm + AS_OFF + st * ASTG;
            const float* Bt = sm + BS_OFF + st * BSTG;
#pragma unroll
            for (int ks = 0; ks < 4; ks++) {
                uint32_t a[2][4];
#pragma unroll
                for (int mt = 0; mt < 2; mt++) {
                    const int r = wm + mt * 16 + gid;
                    const int kb = ks * 8 + tig;
                    a[mt][0] = fu(A[r * 36 + kb]);
                    a[mt][1] = fu(A[(r + 8) * 36 + kb]);
                    a[mt][2] = fu(A[r * 36 + kb + 4]);
                    a[mt][3] = fu(A[(r + 8) * 36 + kb + 4]);
                }
#pragma unroll
                for (int nt = 0; nt < 8; nt++) {
                    const int n = wn * 64 + nt * 8 + gid;
                    const int kb = ks * 8 + tig;
                    uint32_t bb0 = fu(Bt[n * 36 + kb]);
                    uint32_t bb1 = fu(Bt[n * 36 + kb + 4]);
                    mma8(acc1[0][nt], a[0][0], a[0][1], a[0][2], a[0][3], bb0, bb1);
                    mma8(acc1[1][nt], a[1][0], a[1][1], a[1][2], a[1][3], bb0, bb1);
                }
            }
            __syncthreads();
            if (c < 61)       issue_g1(c + 3, n1, (c + 3) % 3, tid, smb, nbh_s, b0);
            else if (c == 63) issue_g2(n1, 0, BS_OFF, tid, smb);
            CP_COMMIT();
        }

        // -------- epilogue pass: h1 = relu(acc1 + c1), tf32-round, -> Hs --------
        {
            const float* c1p = g_c1 + s * H1n + n1 * 128;
#pragma unroll
            for (int nt = 0; nt < 8; nt++) {
                const int col = wn * 64 + nt * 8 + tig * 2;
                const float2 cv = __ldg((const float2*)(c1p + col));
#pragma unroll
                for (int mt = 0; mt < 2; mt++) {
                    const int r = wm + mt * 16 + gid;
                    float* h0 = sm + HS_OFF + r * HSTR + col;
                    float* h1r = sm + HS_OFF + (r + 8) * HSTR + col;
                    h0[0]  = __uint_as_float(f2tf32(fmaxf(acc1[mt][nt][0] + cv.x, 0.f)));
                    h0[1]  = __uint_as_float(f2tf32(fmaxf(acc1[mt][nt][1] + cv.y, 0.f)));
                    h1r[0] = __uint_as_float(f2tf32(fmaxf(acc1[mt][nt][2] + cv.x, 0.f)));
                    h1r[1] = __uint_as_float(f2tf32(fmaxf(acc1[mt][nt][3] + cv.y, 0.f)));
                }
            }
        }
        __syncthreads();
        issue_g2(n1, 1, AS_OFF, tid, smb);
        CP_COMMIT();

        // -------- GEMM2 partial: k = n1*128 .. +128, 4 chunks of 32 --------
        // Buffer parity: chunk kc lives in (kc odd ? AS_OFF : BS_OFF).
        for (int kc = 0; kc < 4; kc++) {
            CP_WAIT1();
            __syncthreads();
            const float* A2 = sm + HS_OFF + kc * 32;
            const float* B2 = sm + ((kc & 1) ? AS_OFF : BS_OFF);
#pragma unroll
            for (int ks = 0; ks < 4; ks++) {
                uint32_t a[2][4];
#pragma unroll
                for (int mt = 0; mt < 2; mt++) {
                    const int r = wm + mt * 16 + gid;
                    const int kb = ks * 8 + tig;
                    a[mt][0] = fu(A2[r * HSTR + kb]);
                    a[mt][1] = fu(A2[(r + 8) * HSTR + kb]);
                    a[mt][2] = fu(A2[r * HSTR + kb + 4]);
                    a[mt][3] = fu(A2[(r + 8) * HSTR + kb + 4]);
                }
#pragma unroll
                for (int nt = 0; nt < 16; nt++) {
                    const int n = wn * 128 + nt * 8 + gid;
                    const int kb = ks * 8 + tig;
                    uint32_t bb0 = fu(B2[n * 36 + kb]);
                    uint32_t bb1 = fu(B2[n * 36 + kb + 4]);
                    mma8(acc2[0][nt], a[0][0], a[0][1], a[0][2], a[0][3], bb0, bb1);
                    mma8(acc2[1][nt], a[1][0], a[1][1], a[1][2], a[1][3], bb0, bb1);
                }
            }
            __syncthreads();
            // FIX (R3 bug): chunk kc+2 has same parity as kc -> same buffer as
            // the one just consumed, NOT the one still in flight.
            if (kc < 2) issue_g2(n1, kc + 2, (kc & 1) ? AS_OFF : BS_OFF, tid, smb);
            CP_COMMIT();
        }
    }

    // -------- final epilogue: relu(acc2 + b2) -> atomicMax --------
#pragma unroll
    for (int nt = 0; nt < 16; nt++) {
        const int n2 = wn * 128 + nt * 8 + tig * 2;
        const float2 bv = __ldg((const float2*)(b2 + n2));
#pragma unroll
        for (int mt = 0; mt < 2; mt++) {
            const int r = b0 + wm + mt * 16 + gid;
            float v0 = fmaxf(acc2[mt][nt][0] + bv.x, 0.f);
            float v1 = fmaxf(acc2[mt][nt][1] + bv.y, 0.f);
            float v2 = fmaxf(acc2[mt][nt][2] + bv.x, 0.f);
            float v3 = fmaxf(acc2[mt][nt][3] + bv.y, 0.f);
            atomicMax(&g_m[r * H2n + n2],            __float_as_uint(v0));
            atomicMax(&g_m[r * H2n + n2 + 1],        __float_as_uint(v1));
            atomicMax(&g_m[(r + 8) * H2n + n2],      __float_as_uint(v2));
            atomicMax(&g_m[(r + 8) * H2n + n2 + 1],  __float_as_uint(v3));
        }
    }
}

// ---------------- finalize ----------------
__global__ void finalize_kernel(const float* __restrict__ Wd,
                                const float* __restrict__ bd,
                                float* __restrict__ out) {
    __shared__ float red[256];
    const int b = blockIdx.x, t = threadIdx.x;
    red[t] = __uint_as_float(g_m[b * H2n + t]) * Wd[t];
    __syncthreads();
#pragma unroll
    for (int st = 128; st > 0; st >>= 1) {
        if (t < st) red[t] += red[t + st];
        __syncthreads();
    }
    if (t == 0) out[b] = red[0] + bd[0];
}

extern "C" void kernel_launch(void* const* d_in, const int* in_sizes, int n_in,
                              void* d_out, int out_size) {
    const float* x    = (const float*)d_in[0];
    const int*   nbh  = (const int*)  d_in[1];
    const float* dist = (const float*)d_in[2];
    const float* W1   = (const float*)d_in[3];
    const float* b1   = (const float*)d_in[4];
    const float* W2   = (const float*)d_in[5];
    const float* b2   = (const float*)d_in[6];
    const float* Wd   = (const float*)d_in[7];
    const float* bd   = (const float*)d_in[8];
    float* out = (float*)d_out;

    static bool attr_set = false;
    if (!attr_set) {
        cudaFuncSetAttribute(fused_mma_kernel,
                             cudaFuncAttributeMaxDynamicSharedMemorySize,
                             SMEM_FLOATS * sizeof(float));
        attr_set = true;
    }

    zero_m_kernel<<<(Bn * H2n + 255) / 256, 256>>>();
    prep_xr_kernel<<<(Bn * Sn * Fn) / 256, 256>>>(x);
    prep_w1t_kernel<<<(H1n * 2048) / 256, 256>>>(W1);
    prep_w2t_kernel<<<(H2n * H1n) / 256, 256>>>(W2);
    prep_c1_kernel<<<Sn, H1n>>>(W1, b1, dist);
    fused_mma_kernel<<<dim3(2, Sn), 256, SMEM_FLOATS * sizeof(float)>>>(nbh, b2);
    finalize_kernel<<<Bn, H2n>>>(Wd, bd, out);
}

// round 5
// speedup vs baseline: 6.0457x; 1.7397x over previous
#include <cuda_runtime.h>
#include <cuda_fp16.h>
#include <cstdint>

#define Bn 256
#define Sn 512
#define Kn 32
#define Fn 64
#define H1n 512
#define H2n 256

// ---------------- device scratch (allocation-free rule) ----------------
__device__ float    g_c1[Sn * H1n];        // fp32: b1 + dist-column contribution
__device__ unsigned g_m[Bn * H2n];         // bits of max_s relu(h2)
__device__ __half   g_w1t[H1n * 2048];     // [n][k], k = nb*64+f, fp16
__device__ __half   g_w2t[H2n * H1n];      // [n2][h1], fp16
__device__ __half   g_xr[Bn * Sn * Fn];    // fp16 x

// ---------------- smem layout (bytes) ----------------
// A/B tiles: rows of 32 halves (64B data) padded to 80B stride -> conflict-free
// LDSM (20 words/row: 8 rows cover all 32 banks).
#define ASTGB 10240u                 // 128 rows * 80B, one stage
#define AS_B 0u
#define BS_B 40960u                  // 4 stages of A
#define HS_B 81920u                  // 4 stages of B
#define HROWB 272u                   // 136 halves (128 + 8 pad), 68 words/row
#define SMEM_BYTES (81920 + 128 * 272)   // 116736

// ---------------- PTX helpers ----------------
__device__ __forceinline__ uint32_t smem_u32(const void* p) {
    uint32_t a;
    asm("{ .reg .u64 t; cvta.to.shared.u64 t, %1; cvt.u32.u64 %0, t; }" : "=r"(a) : "l"(p));
    return a;
}
__device__ __forceinline__ void cpasync16(uint32_t s, const void* g) {
    asm volatile("cp.async.cg.shared.global [%0], [%1], 16;" :: "r"(s), "l"(g));
}
#define CP_COMMIT() asm volatile("cp.async.commit_group;")
#define CP_WAIT2()  asm volatile("cp.async.wait_group 2;")
#define CP_WAIT1()  asm volatile("cp.async.wait_group 1;")

#define LDSM4(r0, r1, r2, r3, addr) \
    asm volatile("ldmatrix.sync.aligned.m8n8.x4.shared.b16 {%0,%1,%2,%3}, [%4];" \
        : "=r"(r0), "=r"(r1), "=r"(r2), "=r"(r3) : "r"(addr))

__device__ __forceinline__ void mma16(float* d, const uint32_t* a,
                                      uint32_t b0, uint32_t b1) {
    asm volatile(
        "mma.sync.aligned.m16n8k16.row.col.f32.f16.f16.f32 "
        "{%0,%1,%2,%3}, {%4,%5,%6,%7}, {%8,%9}, {%0,%1,%2,%3};"
        : "+f"(d[0]), "+f"(d[1]), "+f"(d[2]), "+f"(d[3])
        : "r"(a[0]), "r"(a[1]), "r"(a[2]), "r"(a[3]), "r"(b0), "r"(b1));
}

// ---------------- prep kernels ----------------
__global__ void zero_m_kernel() {
    int i = blockIdx.x * blockDim.x + threadIdx.x;
    if (i < Bn * H2n) g_m[i] = 0u;
}
__global__ void prep_xr_kernel(const float* __restrict__ x) {
    int i = blockIdx.x * 256 + threadIdx.x;
    g_xr[i] = __float2half_rn(x[i]);
}
__global__ void prep_w1t_kernel(const float* __restrict__ W1) {
    int idx = blockIdx.x * 256 + threadIdx.x;   // 512*2048
    int k = idx & 2047, n = idx >> 11;
    int row = (k >> 6) * 65 + (k & 63);
    g_w1t[(size_t)n * 2048 + k] = __float2half_rn(W1[(size_t)row * H1n + n]);
}
__global__ void prep_w2t_kernel(const float* __restrict__ W2) {
    int idx = blockIdx.x * 256 + threadIdx.x;   // 256*512
    int h = idx & 511, n = idx >> 9;
    g_w2t[(size_t)n * H1n + h] = __float2half_rn(W2[(size_t)h * H2n + n]);
}
__global__ void prep_c1_kernel(const float* __restrict__ W1,
                               const float* __restrict__ b1,
                               const float* __restrict__ dist) {
    int s = blockIdx.x, h = threadIdx.x;
    float acc = b1[h];
#pragma unroll
    for (int k = 0; k < Kn; k++)
        acc = fmaf(dist[s * Kn + k], W1[(k * 65 + 64) * H1n + h], acc);
    g_c1[s * H1n + h] = acc;
}

// ---------------- load helpers (256 threads) ----------------
// GEMM1 chunk c: A = gathered x rows [b0..b0+127], 32 halves from f0;
//               B = W1t rows [n1*128 .. +127], 32 halves from c*32.
__device__ __forceinline__ void issue_g1(int c, int n1, int st, int tid,
                                         uint32_t smb, const int* __restrict__ nbh_s,
                                         int b0) {
    const int nb = c >> 1, f0 = (c & 1) * 32;
    const int sidx = __ldg(&nbh_s[nb]);
    const uint32_t ab = smb + AS_B + (uint32_t)st * ASTGB;
    const __half* asrc = g_xr + ((size_t)b0 * Sn + sidx) * Fn + f0;
#pragma unroll
    for (int p = 0; p < 2; p++) {
        int u = tid + p * 256; int r = u >> 2, q = u & 3;
        cpasync16(ab + (uint32_t)(r * 80 + q * 16),
                  asrc + (size_t)r * (Sn * Fn) + q * 8);
    }
    const uint32_t bb = smb + BS_B + (uint32_t)st * ASTGB;
    const __half* bsrc = g_w1t + (size_t)(n1 * 128) * 2048 + c * 32;
#pragma unroll
    for (int p = 0; p < 2; p++) {
        int u = tid + p * 256; int r = u >> 2, q = u & 3;
        cpasync16(bb + (uint32_t)(r * 80 + q * 16),
                  bsrc + (size_t)r * 2048 + q * 8);
    }
}
// GEMM2 chunk kc: W2t rows 0..255, 32 halves from n1*128 + kc*32.
// Occupies TWO ring stages (20480B) at bufoff.
__device__ __forceinline__ void issue_g2(int n1, int kc, uint32_t bufoff, int tid,
                                         uint32_t smb) {
    const uint32_t bb = smb + bufoff;
    const __half* bsrc = g_w2t + n1 * 128 + kc * 32;
#pragma unroll
    for (int p = 0; p < 4; p++) {
        int u = tid + p * 256; int r = u >> 2, q = u & 3;
        cpasync16(bb + (uint32_t)(r * 80 + q * 16),
                  bsrc + (size_t)r * H1n + q * 8);
    }
}

// ---------------- fused fp16 mma kernel ----------------
__global__ __launch_bounds__(256, 1)
void fused_mma_kernel(const int* __restrict__ nbh, const float* __restrict__ b2) {
    extern __shared__ char smc[];
    const int tid = threadIdx.x, lane = tid & 31, wid = tid >> 5;
    const int gid = lane >> 2, tig = lane & 3;
    const int wm = (wid >> 1) * 32;     // warp M offset (0,32,64,96)
    const int wn = wid & 1;             // warp N half
    const int s = blockIdx.y, b0 = blockIdx.x * 128;
    const int* nbh_s = nbh + s * Kn;
    const uint32_t smb = smem_u32(smc);

    // ldmatrix lane addressing (fixed per thread)
    const uint32_t a_lrow = (uint32_t)(lane & 15) * 80u + (uint32_t)(lane >> 4) * 16u;
    const int bg = lane >> 3;
    const uint32_t b_lrow = (uint32_t)(((bg >> 1) * 8) + (lane & 7)) * 80u
                          + (uint32_t)(bg & 1) * 16u;

    float acc2[2][16][4];
#pragma unroll
    for (int mt = 0; mt < 2; mt++)
#pragma unroll
        for (int nt = 0; nt < 16; nt++)
#pragma unroll
            for (int i = 0; i < 4; i++) acc2[mt][nt][i] = 0.f;

    for (int n1 = 0; n1 < 4; n1++) {
        float acc1[2][8][4];
#pragma unroll
        for (int mt = 0; mt < 2; mt++)
#pragma unroll
            for (int nt = 0; nt < 8; nt++)
#pragma unroll
                for (int i = 0; i < 4; i++) acc1[mt][nt][i] = 0.f;

        // prologue: 3 chunks in flight (4-stage ring, distance 3)
#pragma unroll
        for (int c = 0; c < 3; c++) {
            issue_g1(c, n1, c, tid, smb, nbh_s, b0);
            CP_COMMIT();
        }

        // -------- GEMM1 mainloop: 64 chunks of k=32 --------
        for (int c = 0; c < 64; c++) {
            CP_WAIT2();
            __syncthreads();
            // prefetch into stage (c+3)&3 == (c-1)&3, freed last iter (barrier above)
            if (c < 61) issue_g1(c + 3, n1, (c + 3) & 3, tid, smb, nbh_s, b0);
            CP_COMMIT();

            const uint32_t st = (uint32_t)(c & 3) * ASTGB;
            const uint32_t aT = smb + AS_B + st + (uint32_t)wm * 80u + a_lrow;
            const uint32_t bT = smb + BS_B + st + (uint32_t)(wn * 64) * 80u + b_lrow;
#pragma unroll
            for (int ks = 0; ks < 2; ks++) {
                uint32_t a0[4], a1[4];
                LDSM4(a0[0], a0[1], a0[2], a0[3], aT + ks * 32);
                LDSM4(a1[0], a1[1], a1[2], a1[3], aT + 1280 + ks * 32);
#pragma unroll
                for (int j = 0; j < 4; j++) {
                    uint32_t r0, r1, r2, r3;
                    LDSM4(r0, r1, r2, r3, bT + (uint32_t)j * 1280u + ks * 32);
                    mma16(acc1[0][2 * j],     a0, r0, r1);
                    mma16(acc1[0][2 * j + 1], a0, r2, r3);
                    mma16(acc1[1][2 * j],     a1, r0, r1);
                    mma16(acc1[1][2 * j + 1], a1, r2, r3);
                }
            }
        }

        // safe without extra barrier: BS stages 0,1 last read at c=60,61;
        // every thread passed the c=63 top barrier (=> finished c=62).
        issue_g2(n1, 0, BS_B, tid, smb);
        CP_COMMIT();

        // -------- epilogue: h1 = relu(acc1 + c1) -> fp16 -> Hs --------
        {
            const float* c1p = g_c1 + s * H1n + n1 * 128;
#pragma unroll
            for (int nt = 0; nt < 8; nt++) {
                const int col = wn * 64 + nt * 8 + tig * 2;
                const float2 cv = __ldg((const float2*)(c1p + col));
#pragma unroll
                for (int mt = 0; mt < 2; mt++) {
                    const int r = wm + mt * 16 + gid;
                    __half2* h0 = (__half2*)(smc + HS_B + (uint32_t)r * HROWB + col * 2);
                    __half2* h1r = (__half2*)(smc + HS_B + (uint32_t)(r + 8) * HROWB + col * 2);
                    *h0  = __floats2half2_rn(fmaxf(acc1[mt][nt][0] + cv.x, 0.f),
                                             fmaxf(acc1[mt][nt][1] + cv.y, 0.f));
                    *h1r = __floats2half2_rn(fmaxf(acc1[mt][nt][2] + cv.x, 0.f),
                                             fmaxf(acc1[mt][nt][3] + cv.y, 0.f));
                }
            }
        }
        __syncthreads();   // Hs visible; AS stages 0,1 free
        issue_g2(n1, 1, AS_B, tid, smb);
        CP_COMMIT();

        // -------- GEMM2 partial: k = n1*128..+128, 4 chunks of 32 --------
        // chunk kc parity: even -> BS region, odd -> AS region
        for (int kc = 0; kc < 4; kc++) {
            CP_WAIT1();
            __syncthreads();
            const uint32_t aT = smb + HS_B + (uint32_t)wm * HROWB
                              + (uint32_t)(lane & 15) * HROWB
                              + (uint32_t)(lane >> 4) * 16u + (uint32_t)kc * 64u;
            const uint32_t bT = smb + ((kc & 1) ? AS_B : BS_B)
                              + (uint32_t)(wn * 128) * 80u + b_lrow;
#pragma unroll
            for (int ks = 0; ks < 2; ks++) {
                uint32_t a0[4], a1[4];
                LDSM4(a0[0], a0[1], a0[2], a0[3], aT + ks * 32);
                LDSM4(a1[0], a1[1], a1[2], a1[3], aT + 16 * HROWB + ks * 32);
#pragma unroll
                for (int j = 0; j < 8; j++) {
                    uint32_t r0, r1, r2, r3;
                    LDSM4(r0, r1, r2, r3, bT + (uint32_t)j * 1280u + ks * 32);
                    mma16(acc2[0][2 * j],     a0, r0, r1);
                    mma16(acc2[0][2 * j + 1], a0, r2, r3);
                    mma16(acc2[1][2 * j],     a1, r0, r1);
                    mma16(acc2[1][2 * j + 1], a1, r2, r3);
                }
            }
            __syncthreads();
            // chunk kc+2 shares parity with kc -> reuse buffer just consumed
            if (kc < 2) issue_g2(n1, kc + 2, (kc & 1) ? AS_B : BS_B, tid, smb);
            CP_COMMIT();
        }
        // post-kc3 barrier above guards next prologue's stage reuse
    }

    // -------- final epilogue: relu(acc2 + b2) -> atomicMax --------
#pragma unroll
    for (int nt = 0; nt < 16; nt++) {
        const int n2 = wn * 128 + nt * 8 + tig * 2;
        const float2 bv = __ldg((const float2*)(b2 + n2));
#pragma unroll
        for (int mt = 0; mt < 2; mt++) {
            const int r = b0 + wm + mt * 16 + gid;
            float v0 = fmaxf(acc2[mt][nt][0] + bv.x, 0.f);
            float v1 = fmaxf(acc2[mt][nt][1] + bv.y, 0.f);
            float v2 = fmaxf(acc2[mt][nt][2] + bv.x, 0.f);
            float v3 = fmaxf(acc2[mt][nt][3] + bv.y, 0.f);
            atomicMax(&g_m[r * H2n + n2],           __float_as_uint(v0));
            atomicMax(&g_m[r * H2n + n2 + 1],       __float_as_uint(v1));
            atomicMax(&g_m[(r + 8) * H2n + n2],     __float_as_uint(v2));
            atomicMax(&g_m[(r + 8) * H2n + n2 + 1], __float_as_uint(v3));
        }
    }
}

// ---------------- finalize ----------------
__global__ void finalize_kernel(const float* __restrict__ Wd,
                                const float* __restrict__ bd,
                                float* __restrict__ out) {
    __shared__ float red[256];
    const int b = blockIdx.x, t = threadIdx.x;
    red[t] = __uint_as_float(g_m[b * H2n + t]) * Wd[t];
    __syncthreads();
#pragma unroll
    for (int st = 128; st > 0; st >>= 1) {
        if (t < st) red[t] += red[t + st];
        __syncthreads();
    }
    if (t == 0) out[b] = red[0] + bd[0];
}

extern "C" void kernel_launch(void* const* d_in, const int* in_sizes, int n_in,
                              void* d_out, int out_size) {
    const float* x    = (const float*)d_in[0];
    const int*   nbh  = (const int*)  d_in[1];
    const float* dist = (const float*)d_in[2];
    const float* W1   = (const float*)d_in[3];
    const float* b1   = (const float*)d_in[4];
    const float* W2   = (const float*)d_in[5];
    const float* b2   = (const float*)d_in[6];
    const float* Wd   = (const float*)d_in[7];
    const float* bd   = (const float*)d_in[8];
    float* out = (float*)d_out;

    static bool attr_set = false;
    if (!attr_set) {
        cudaFuncSetAttribute(fused_mma_kernel,
                             cudaFuncAttributeMaxDynamicSharedMemorySize, SMEM_BYTES);
        attr_set = true;
    }

    zero_m_kernel<<<(Bn * H2n + 255) / 256, 256>>>();
    prep_xr_kernel<<<(Bn * Sn * Fn) / 256, 256>>>(x);
    prep_w1t_kernel<<<(H1n * 2048) / 256, 256>>>(W1);
    prep_w2t_kernel<<<(H2n * H1n) / 256, 256>>>(W2);
    prep_c1_kernel<<<Sn, H1n>>>(W1, b1, dist);
    fused_mma_kernel<<<dim3(2, Sn), 256, SMEM_BYTES>>>(nbh, b2);
    finalize_kernel<<<Bn, H2n>>>(Wd, bd, out);
}

// round 8
// speedup vs baseline: 6.9733x; 1.1534x over previous
#include <cuda_runtime.h>
#include <cuda_fp16.h>
#include <cstdint>

#define Bn 256
#define Sn 512
#define Kn 32
#define Fn 64
#define H1n 512
#define H2n 256

// ---------------- device scratch (allocation-free rule) ----------------
__device__ float    g_c1[Sn * H1n];        // fp32: b1 + dist-column contribution
__device__ unsigned g_m[Bn * H2n];         // bits of max_s relu(h2)
__device__ __half   g_w1t[H1n * 2048];     // [n][k], k = nb*64+f, fp16
__device__ __half   g_w2t[H2n * H1n];      // [n2][h1], fp16
__device__ __half   g_xr[Bn * Sn * Fn];    // fp16 x

// ---------------- smem layout (bytes) ----------------
// Stage block: A tile (128 rows x 64 halves, 144B row stride) then B tile.
// 144B stride = 36 words (== 4 mod 32) -> conflict-free 8-row LDSM phases.
#define ROWB 144u
#define TILEB (128u * ROWB)          // 18432
#define STGB  (2u * TILEB)           // 36864 per stage (A at +0, B at +TILEB)
#define HS_B  (3u * STGB)            // 110592
#define HROWB 272u                   // 128 halves data + pad
#define SMEM_BYTES (110592 + 128 * 272)   // 145408

// ---------------- PTX helpers ----------------
__device__ __forceinline__ uint32_t smem_u32(const void* p) {
    uint32_t a;
    asm("{ .reg .u64 t; cvta.to.shared.u64 t, %1; cvt.u32.u64 %0, t; }" : "=r"(a) : "l"(p));
    return a;
}
__device__ __forceinline__ void cpasync16(uint32_t s, const void* g) {
    asm volatile("cp.async.cg.shared.global [%0], [%1], 16;" :: "r"(s), "l"(g));
}
#define CP_COMMIT() asm volatile("cp.async.commit_group;")
#define CP_WAIT1()  asm volatile("cp.async.wait_group 1;")
#define CP_WAIT0()  asm volatile("cp.async.wait_group 0;")

#define LDSM4(r0, r1, r2, r3, addr) \
    asm volatile("ldmatrix.sync.aligned.m8n8.x4.shared.b16 {%0,%1,%2,%3}, [%4];" \
        : "=r"(r0), "=r"(r1), "=r"(r2), "=r"(r3) : "r"(addr))

__device__ __forceinline__ void mma16(float* d, const uint32_t* a,
                                      uint32_t b0, uint32_t b1) {
    asm volatile(
        "mma.sync.aligned.m16n8k16.row.col.f32.f16.f16.f32 "
        "{%0,%1,%2,%3}, {%4,%5,%6,%7}, {%8,%9}, {%0,%1,%2,%3};"
        : "+f"(d[0]), "+f"(d[1]), "+f"(d[2]), "+f"(d[3])
        : "r"(a[0]), "r"(a[1]), "r"(a[2]), "r"(a[3]), "r"(b0), "r"(b1));
}

// ---------------- prep kernels ----------------
__global__ void zero_m_kernel() {
    int i = blockIdx.x * blockDim.x + threadIdx.x;
    if (i < Bn * H2n) g_m[i] = 0u;
}
__global__ void prep_xr_kernel(const float* __restrict__ x) {
    int i = blockIdx.x * 256 + threadIdx.x;
    g_xr[i] = __float2half_rn(x[i]);
}
__global__ void prep_w1t_kernel(const float* __restrict__ W1) {
    int idx = blockIdx.x * 256 + threadIdx.x;   // 512*2048
    int k = idx & 2047, n = idx >> 11;
    int row = (k >> 6) * 65 + (k & 63);
    g_w1t[(size_t)n * 2048 + k] = __float2half_rn(W1[(size_t)row * H1n + n]);
}
__global__ void prep_w2t_kernel(const float* __restrict__ W2) {
    int idx = blockIdx.x * 256 + threadIdx.x;   // 256*512
    int h = idx & 511, n = idx >> 9;
    g_w2t[(size_t)n * H1n + h] = __float2half_rn(W2[(size_t)h * H2n + n]);
}
__global__ void prep_c1_kernel(const float* __restrict__ W1,
                               const float* __restrict__ b1,
                               const float* __restrict__ dist) {
    int s = blockIdx.x, h = threadIdx.x;
    float acc = b1[h];
#pragma unroll
    for (int k = 0; k < Kn; k++)
        acc = fmaf(dist[s * Kn + k], W1[(k * 65 + 64) * H1n + h], acc);
    g_c1[s * H1n + h] = acc;
}

// ---------------- load helpers (256 threads) ----------------
// GEMM1 chunk c (= neighbor c): A = x[b0..b0+127, nbh[s,c], 0:64],
//                               B = W1t rows [n1*128..+127], halves [c*64..+64).
// Each tile: 128 rows x 128 bytes -> 1024 x 16B cp.async (4 per thread).
__device__ __forceinline__ void issue_g1(int c, int n1, int st, int tid,
                                         uint32_t smb, const int* __restrict__ nbh_s,
                                         int b0) {
    const int sidx = __ldg(&nbh_s[c]);
    const uint32_t ab = smb + (uint32_t)st * STGB;
    const __half* asrc = g_xr + ((size_t)b0 * Sn + sidx) * Fn;
#pragma unroll
    for (int p = 0; p < 4; p++) {
        int u = tid + p * 256; int r = u >> 3, q = u & 7;
        cpasync16(ab + (uint32_t)r * ROWB + (uint32_t)q * 16u,
                  asrc + (size_t)r * (Sn * Fn) + q * 8);
    }
    const uint32_t bb = ab + TILEB;
    const __half* bsrc = g_w1t + (size_t)(n1 * 128) * 2048 + c * 64;
#pragma unroll
    for (int p = 0; p < 4; p++) {
        int u = tid + p * 256; int r = u >> 3, q = u & 7;
        cpasync16(bb + (uint32_t)r * ROWB + (uint32_t)q * 16u,
                  bsrc + (size_t)r * 2048 + q * 8);
    }
}
// W2 k-half `hk` of n1-block: 256 rows x 64 halves (128B/row) -> full stage region.
__device__ __forceinline__ void issue_g2(int n1, int hk, int st, int tid,
                                         uint32_t smb) {
    const uint32_t bb = smb + (uint32_t)st * STGB;
    const __half* bsrc = g_w2t + n1 * 128 + hk * 64;
#pragma unroll
    for (int p = 0; p < 8; p++) {
        int u = tid + p * 256; int n = u >> 3, q = u & 7;
        cpasync16(bb + (uint32_t)n * ROWB + (uint32_t)q * 16u,
                  bsrc + (size_t)n * H1n + q * 8);
    }
}

// ---------------- fused fp16 mma kernel ----------------
__global__ __launch_bounds__(256, 1)
void fused_mma_kernel(const int* __restrict__ nbh, const float* __restrict__ b2) {
    extern __shared__ char smc[];
    const int tid = threadIdx.x, lane = tid & 31, wid = tid >> 5;
    const int gid = lane >> 2, tig = lane & 3;
    const int wm = (wid >> 1) * 32;     // warp M offset (0,32,64,96)
    const int wn = wid & 1;             // warp N half
    const int s = blockIdx.y, b0 = blockIdx.x * 128;
    const int* nbh_s = nbh + s * Kn;
    const uint32_t smb = smem_u32(smc);

    // ldmatrix lane addressing
    const uint32_t a_lrow = (uint32_t)(lane & 15) * ROWB + (uint32_t)(lane >> 4) * 16u;
    const int bg = lane >> 3;
    const uint32_t b_lrow = (uint32_t)(((bg >> 1) * 8) + (lane & 7)) * ROWB
                          + (uint32_t)(bg & 1) * 16u;
    const uint32_t h_lrow = (uint32_t)(lane & 15) * HROWB + (uint32_t)(lane >> 4) * 16u;

    float acc2[2][16][4];
#pragma unroll
    for (int mt = 0; mt < 2; mt++)
#pragma unroll
        for (int nt = 0; nt < 16; nt++)
#pragma unroll
            for (int i = 0; i < 4; i++) acc2[mt][nt][i] = 0.f;

    for (int n1 = 0; n1 < 4; n1++) {
        float acc1[2][8][4];
#pragma unroll
        for (int mt = 0; mt < 2; mt++)
#pragma unroll
            for (int nt = 0; nt < 8; nt++)
#pragma unroll
                for (int i = 0; i < 4; i++) acc1[mt][nt][i] = 0.f;

        // guard stage0/1 reuse against previous n1's GEMM2 readers
        __syncthreads();
        issue_g1(0, n1, 0, tid, smb, nbh_s, b0);
        CP_COMMIT();
        issue_g1(1, n1, 1, tid, smb, nbh_s, b0);
        CP_COMMIT();

        // -------- GEMM1 mainloop: 32 chunks of k=64 --------
        for (int c = 0; c < 32; c++) {
            CP_WAIT1();
            __syncthreads();
            if (c < 30)       issue_g1(c + 2, n1, (c + 2) % 3, tid, smb, nbh_s, b0);
            else if (c == 30) issue_g2(n1, 0, 2, tid, smb);  // stage2 free (last used c=29)
            else              issue_g2(n1, 1, 0, tid, smb);  // stage0 free (last used c=30)
            CP_COMMIT();

            const uint32_t stb = smb + (uint32_t)(c % 3) * STGB;
            const uint32_t aT = stb + (uint32_t)wm * ROWB + a_lrow;
            const uint32_t bT = stb + TILEB + (uint32_t)(wn * 64) * ROWB + b_lrow;
#pragma unroll
            for (int ks = 0; ks < 4; ks++) {
                uint32_t a0[4], a1[4];
                LDSM4(a0[0], a0[1], a0[2], a0[3], aT + ks * 32);
                LDSM4(a1[0], a1[1], a1[2], a1[3], aT + 16 * ROWB + ks * 32);
#pragma unroll
                for (int j = 0; j < 4; j++) {
                    uint32_t r0, r1, r2, r3;
                    // FIX (R6 bug): each LDSM4 covers 16 B-rows -> step 16*ROWB
                    LDSM4(r0, r1, r2, r3, bT + (uint32_t)j * (16 * ROWB) + ks * 32);
                    mma16(acc1[0][2 * j],     a0, r0, r1);
                    mma16(acc1[0][2 * j + 1], a0, r2, r3);
                    mma16(acc1[1][2 * j],     a1, r0, r1);
                    mma16(acc1[1][2 * j + 1], a1, r2, r3);
                }
            }
        }

        // -------- epilogue: h1 = relu(acc1 + c1) -> fp16 -> Hs --------
        {
            const float* c1p = g_c1 + s * H1n + n1 * 128;
#pragma unroll
            for (int nt = 0; nt < 8; nt++) {
                const int col = wn * 64 + nt * 8 + tig * 2;
                const float2 cv = __ldg((const float2*)(c1p + col));
#pragma unroll
                for (int mt = 0; mt < 2; mt++) {
                    const int r = wm + mt * 16 + gid;
                    __half2* h0 = (__half2*)(smc + HS_B + (uint32_t)r * HROWB + col * 2);
                    __half2* h1r = (__half2*)(smc + HS_B + (uint32_t)(r + 8) * HROWB + col * 2);
                    *h0  = __floats2half2_rn(fmaxf(acc1[mt][nt][0] + cv.x, 0.f),
                                             fmaxf(acc1[mt][nt][1] + cv.y, 0.f));
                    *h1r = __floats2half2_rn(fmaxf(acc1[mt][nt][2] + cv.x, 0.f),
                                             fmaxf(acc1[mt][nt][3] + cv.y, 0.f));
                }
            }
        }

        // -------- GEMM2: 2 chunks of k=64 (W2 halves in stage2 / stage0) --------
#pragma unroll
        for (int kc = 0; kc < 2; kc++) {
            if (kc == 0) CP_WAIT1(); else CP_WAIT0();
            __syncthreads();   // W2 half visible (+ Hs stores on kc=0)
            const uint32_t aT = smb + HS_B + (uint32_t)wm * HROWB + h_lrow
                              + (uint32_t)kc * 128u;
            const uint32_t bT = smb + (uint32_t)(kc == 0 ? 2 : 0) * STGB
                              + (uint32_t)(wn * 128) * ROWB + b_lrow;
#pragma unroll
            for (int ks = 0; ks < 4; ks++) {
                uint32_t a0[4], a1[4];
                LDSM4(a0[0], a0[1], a0[2], a0[3], aT + ks * 32);
                LDSM4(a1[0], a1[1], a1[2], a1[3], aT + 16 * HROWB + ks * 32);
#pragma unroll
                for (int j = 0; j < 8; j++) {
                    uint32_t r0, r1, r2, r3;
                    // FIX (R6 bug): 16-row step here as well
                    LDSM4(r0, r1, r2, r3, bT + (uint32_t)j * (16 * ROWB) + ks * 32);
                    mma16(acc2[0][2 * j],     a0, r0, r1);
                    mma16(acc2[0][2 * j + 1], a0, r2, r3);
                    mma16(acc2[1][2 * j],     a1, r0, r1);
                    mma16(acc2[1][2 * j + 1], a1, r2, r3);
                }
            }
        }
    }

    // -------- final epilogue: relu(acc2 + b2) -> atomicMax --------
#pragma unroll
    for (int nt = 0; nt < 16; nt++) {
        const int n2 = wn * 128 + nt * 8 + tig * 2;
        const float2 bv = __ldg((const float2*)(b2 + n2));
#pragma unroll
        for (int mt = 0; mt < 2; mt++) {
            const int r = b0 + wm + mt * 16 + gid;
            float v0 = fmaxf(acc2[mt][nt][0] + bv.x, 0.f);
            float v1 = fmaxf(acc2[mt][nt][1] + bv.y, 0.f);
            float v2 = fmaxf(acc2[mt][nt][2] + bv.x, 0.f);
            float v3 = fmaxf(acc2[mt][nt][3] + bv.y, 0.f);
            atomicMax(&g_m[r * H2n + n2],           __float_as_uint(v0));
            atomicMax(&g_m[r * H2n + n2 + 1],       __float_as_uint(v1));
            atomicMax(&g_m[(r + 8) * H2n + n2],     __float_as_uint(v2));
            atomicMax(&g_m[(r + 8) * H2n + n2 + 1], __float_as_uint(v3));
        }
    }
}

// ---------------- finalize ----------------
__global__ void finalize_kernel(const float* __restrict__ Wd,
                                const float* __restrict__ bd,
                                float* __restrict__ out) {
    __shared__ float red[256];
    const int b = blockIdx.x, t = threadIdx.x;
    red[t] = __uint_as_float(g_m[b * H2n + t]) * Wd[t];
    __syncthreads();
#pragma unroll
    for (int st = 128; st > 0; st >>= 1) {
        if (t < st) red[t] += red[t + st];
        __syncthreads();
    }
    if (t == 0) out[b] = red[0] + bd[0];
}

extern "C" void kernel_launch(void* const* d_in, const int* in_sizes, int n_in,
                              void* d_out, int out_size) {
    const float* x    = (const float*)d_in[0];
    const int*   nbh  = (const int*)  d_in[1];
    const float* dist = (const float*)d_in[2];
    const float* W1   = (const float*)d_in[3];
    const float* b1   = (const float*)d_in[4];
    const float* W2   = (const float*)d_in[5];
    const float* b2   = (const float*)d_in[6];
    const float* Wd   = (const float*)d_in[7];
    const float* bd   = (const float*)d_in[8];
    float* out = (float*)d_out;

    static bool attr_set = false;
    if (!attr_set) {
        cudaFuncSetAttribute(fused_mma_kernel,
                             cudaFuncAttributeMaxDynamicSharedMemorySize, SMEM_BYTES);
        attr_set = true;
    }

    zero_m_kernel<<<(Bn * H2n + 255) / 256, 256>>>();
    prep_xr_kernel<<<(Bn * Sn * Fn) / 256, 256>>>(x);
    prep_w1t_kernel<<<(H1n * 2048) / 256, 256>>>(W1);
    prep_w2t_kernel<<<(H2n * H1n) / 256, 256>>>(W2);
    prep_c1_kernel<<<Sn, H1n>>>(W1, b1, dist);
    fused_mma_kernel<<<dim3(2, Sn), 256, SMEM_BYTES>>>(nbh, b2);
    finalize_kernel<<<Bn, H2n>>>(Wd, bd, out);
}